// round 16
// baseline (speedup 1.0000x reference)
#include <cuda_runtime.h>
#include <cuda_bf16.h>
#include <cuda_fp16.h>
#include <math.h>
#include <cstdint>

#define NB 4
#define NH 16
#define DH 64
#define SQ 1024
#define LI 128
#define HIDDEN 1024
#define BHN (NB * NH)

// ---------------- scratch (all fp16, single-term) ---------------------------
__device__ __align__(16) __half g_Qf[BHN * SQ * DH];
__device__ __align__(16) __half g_Kf[BHN * SQ * DH];
__device__ __align__(16) __half g_Vf[BHN * SQ * DH];
__device__ __align__(16) __half g_IKf[BHN * LI * DH];
__device__ __align__(16) __half g_IVf[BHN * LI * DH];
__device__ __align__(16) __half g_Ef[2048 * DH];

__device__ __align__(16) __half g_Xh[NB * SQ * HIDDEN];
__device__ __align__(16) __half g_IXh[NB * LI * HIDDEN];
__device__ __align__(16) __half g_Wh[3 * HIDDEN * HIDDEN];   // [n(3072)][k(1024)]

// ---------------- helpers ---------------------------------------------------
__device__ __forceinline__ uint32_t smem_u32(const void* p) {
    uint32_t a;
    asm("{ .reg .u64 t; cvta.to.shared.u64 t, %1; cvt.u32.u64 %0, t; }" : "=r"(a) : "l"(p));
    return a;
}
__device__ __forceinline__ void ldsm4(uint32_t& r0, uint32_t& r1, uint32_t& r2,
                                      uint32_t& r3, uint32_t addr) {
    asm volatile("ldmatrix.sync.aligned.m8n8.x4.shared.b16 {%0,%1,%2,%3}, [%4];"
                 : "=r"(r0), "=r"(r1), "=r"(r2), "=r"(r3) : "r"(addr));
}
__device__ __forceinline__ void ldsm4t(uint32_t& r0, uint32_t& r1, uint32_t& r2,
                                       uint32_t& r3, uint32_t addr) {
    asm volatile("ldmatrix.sync.aligned.m8n8.x4.trans.shared.b16 {%0,%1,%2,%3}, [%4];"
                 : "=r"(r0), "=r"(r1), "=r"(r2), "=r"(r3) : "r"(addr));
}
__device__ __forceinline__ void mma16816h(float* c, uint32_t a0, uint32_t a1,
                                          uint32_t a2, uint32_t a3,
                                          uint32_t b0, uint32_t b1) {
    asm volatile(
        "mma.sync.aligned.m16n8k16.row.col.f32.f16.f16.f32 "
        "{%0,%1,%2,%3}, {%4,%5,%6,%7}, {%8,%9}, {%0,%1,%2,%3};"
        : "+f"(c[0]), "+f"(c[1]), "+f"(c[2]), "+f"(c[3])
        : "r"(a0), "r"(a1), "r"(a2), "r"(a3), "r"(b0), "r"(b1));
}
__device__ __forceinline__ uint32_t pk2h(float a, float b) {
    __half2 t = __floats2half2_rn(a, b);
    return *(uint32_t*)&t;
}
__device__ __forceinline__ void cpasync16(uint32_t dst, const void* src) {
    asm volatile("cp.async.cg.shared.global [%0], [%1], 16;" :: "r"(dst), "l"(src));
}
#define CP_COMMIT() asm volatile("cp.async.commit_group;" ::: "memory")
#define CP_WAIT(n)  asm volatile("cp.async.wait_group %0;" :: "n"(n) : "memory")

// ---------------------------------------------------------------------------
// Conversions: X / X-instruct / E / W merged (single-term fp16 everywhere).
// ---------------------------------------------------------------------------
#define NX_MAIN (NB * SQ * HIDDEN / 4 / 256)
#define NX_INST (NB * LI * HIDDEN / 4 / 256)
#define NX_E    (2048 * 64 / 256)
#define NX_W    3072
#define NX_BASE3 (NX_MAIN + NX_INST + NX_E)

__global__ __launch_bounds__(256)
void conv_all(const float4* __restrict__ xm, __half* __restrict__ dm,
              const float4* __restrict__ xi, __half* __restrict__ di,
              const float* __restrict__ dist, __half* __restrict__ eh,
              const float* __restrict__ Wq, const float* __restrict__ Wk,
              const float* __restrict__ Wv, __half* __restrict__ wdst)
{
    __shared__ float t[32][33];
    int blk = blockIdx.x;
    if (blk >= NX_BASE3) {
        int wblk = blk - NX_BASE3;
        int z = wblk >> 10, rem = wblk & 1023;
        int bx = rem & 31, by = rem >> 5;
        const float* W = (z == 0) ? Wq : (z == 1) ? Wk : Wv;
        int tx = threadIdx.x & 31, ty = threadIdx.x >> 5;
        int n = bx * 32 + tx, k0 = by * 32;
#pragma unroll
        for (int j = 0; j < 4; j++)
            t[ty + 8 * j][tx] = W[(size_t)(k0 + ty + 8 * j) * HIDDEN + n];
        __syncthreads();
        size_t nrow = (size_t)z * HIDDEN + bx * 32;
#pragma unroll
        for (int j = 0; j < 4; j++)
            wdst[(nrow + ty + 8 * j) * HIDDEN + k0 + tx] = __float2half(t[tx][ty + 8 * j]);
        return;
    }
    if (blk >= NX_MAIN + NX_INST) {
        int i = (blk - NX_MAIN - NX_INST) * 256 + threadIdx.x;
        float v = (i < 2047 * 64) ? dist[i] : 0.f;
        eh[i] = __float2half(v);
        return;
    }
    const float4* src = (blk < NX_MAIN) ? xm : xi;
    __half* dst = (blk < NX_MAIN) ? dm : di;
    int i = ((blk < NX_MAIN) ? blk : blk - NX_MAIN) * 256 + threadIdx.x;
    float4 v = src[i];
    uint2 H;
    H.x = pk2h(v.x, v.y);
    H.y = pk2h(v.z, v.w);
    *(uint2*)(dst + (size_t)i * 4) = H;
}

// ---------------------------------------------------------------------------
// Merged projection GEMM: K=1024 fp16, all outputs single fp16 (unchanged).
// ---------------------------------------------------------------------------
#define AST 72
#define TA (128 * AST * 2)
#define TB (256 * AST * 2)
#define GEMM_SMEM (2 * (TA + TB))

__global__ __launch_bounds__(256, 1)
void gemm_mma(const __half* __restrict__ Am, const __half* __restrict__ Ai,
              const __half* __restrict__ Bm,
              const float* __restrict__ bq, const float* __restrict__ bk,
              const float* __restrict__ bv,
              __half* oQf, __half* oKf, __half* oVf,
              __half* oIKf, __half* oIVf)
{
    extern __shared__ char smem[];
    const uint32_t sb = smem_u32(smem);
    const int tid = threadIdx.x, warp = tid >> 5, lane = tid & 31;

    const __half* A;
    int msh, Slen, m0, n0g, inst;
    {
        int blk = blockIdx.x;
        if (blk < 384) {
            A = Am; msh = 10; Slen = SQ; inst = 0;
            m0 = (blk / 12) * 128; n0g = (blk % 12) * 256;
        } else {
            blk -= 384;
            A = Ai; msh = 7; Slen = LI; inst = 1;
            m0 = (blk / 8) * 128; n0g = 1024 + (blk % 8) * 256;
        }
    }
    const int wm = (warp >> 2) * 64, wn = (warp & 3) * 64;

    const int cr = tid >> 3, cko = (tid & 7) * 8;
    const __half* Ag = A + (size_t)(m0 + cr) * HIDDEN + cko;
    const __half* Bg = Bm + (size_t)(n0g + cr) * HIDDEN + cko;
    const uint32_t sAo = (cr * AST + cko) * 2;

    float acc[4][8][4];
#pragma unroll
    for (int i = 0; i < 4; i++)
#pragma unroll
        for (int j = 0; j < 8; j++)
#pragma unroll
            for (int p = 0; p < 4; p++) acc[i][j][p] = 0.f;

#pragma unroll
    for (int i = 0; i < 4; i++)
        cpasync16(sb + sAo + i * 32 * AST * 2, Ag + (size_t)(i * 32) * HIDDEN);
#pragma unroll
    for (int i = 0; i < 8; i++)
        cpasync16(sb + TA + sAo + i * 32 * AST * 2, Bg + (size_t)(i * 32) * HIDDEN);
    CP_COMMIT();

    const int NCH = 16;
    for (int c = 0; c < NCH; c++) {
        const int p = c & 1;
        if (c + 1 < NCH) {
            const int pn = (c + 1) & 1;
            const int koff = (c + 1) * 64;
#pragma unroll
            for (int i = 0; i < 4; i++)
                cpasync16(sb + pn * (TA + TB) + sAo + i * 32 * AST * 2,
                          Ag + (size_t)(i * 32) * HIDDEN + koff);
#pragma unroll
            for (int i = 0; i < 8; i++)
                cpasync16(sb + pn * (TA + TB) + TA + sAo + i * 32 * AST * 2,
                          Bg + (size_t)(i * 32) * HIDDEN + koff);
            CP_COMMIT();
            CP_WAIT(1);
        } else {
            CP_WAIT(0);
        }
        __syncthreads();

        const uint32_t aw = sb + p * (TA + TB) +
                            ((wm + (lane & 15)) * AST + (lane >> 4) * 8) * 2;
        const uint32_t bw = sb + p * (TA + TB) + TA +
                            ((wn + (lane & 15)) * AST + (lane >> 4) * 8) * 2;
#pragma unroll
        for (int k16 = 0; k16 < 4; k16++) {
            const uint32_t ko = k16 * 32;
            uint32_t a[4][4], b[4][4];
#pragma unroll
            for (int mt = 0; mt < 4; mt++)
                ldsm4(a[mt][0], a[mt][1], a[mt][2], a[mt][3],
                      aw + mt * 16 * AST * 2 + ko);
#pragma unroll
            for (int nb = 0; nb < 4; nb++)
                ldsm4(b[nb][0], b[nb][1], b[nb][2], b[nb][3],
                      bw + nb * 16 * AST * 2 + ko);
#pragma unroll
            for (int mt = 0; mt < 4; mt++)
#pragma unroll
                for (int nb = 0; nb < 4; nb++) {
                    mma16816h(acc[mt][2 * nb], a[mt][0], a[mt][1], a[mt][2], a[mt][3],
                              b[nb][0], b[nb][2]);
                    mma16816h(acc[mt][2 * nb + 1], a[mt][0], a[mt][1], a[mt][2], a[mt][3],
                              b[nb][1], b[nb][3]);
                }
        }
        __syncthreads();
    }

#pragma unroll
    for (int nt = 0; nt < 8; nt++) {
        const int n = n0g + wn + nt * 8 + (lane & 3) * 2;
        const int wsel = n >> 10, nn = n & 1023;
        const float* bias = (wsel == 0) ? bq : (wsel == 1) ? bk : bv;
        const float b0 = bias[nn], b1 = bias[nn + 1];
        const size_t hoff = ((size_t)(nn >> 6)) * Slen;
        const int d = nn & 63;
        __half* pv = inst ? ((wsel == 1) ? oIKf : oIVf)
                          : ((wsel == 0) ? oQf : (wsel == 1) ? oKf : oVf);
#pragma unroll
        for (int mt = 0; mt < 4; mt++)
#pragma unroll
            for (int half = 0; half < 2; half++) {
                const int r = m0 + wm + mt * 16 + (lane >> 2) + half * 8;
                const int bb = r >> msh, t = r - (bb << msh);
                float vx = acc[mt][nt][half * 2 + 0] + b0;
                float vy = acc[mt][nt][half * 2 + 1] + b1;
                size_t off = ((size_t)bb * NH * Slen + hoff + t) * DH + d;
                *(uint32_t*)(pv + off) = pk2h(vx, vy);
            }
    }
}

// ---------------------------------------------------------------------------
// Attention v8: R14 structure + one-tile prefetch of K/V/E/amask.
// K,V double-buffered; E triple-buffered (sliding window needs 2 live + 1
// prefetch target); probs alias P2 (bar-guarded). 3 syncthreads/tile.
// ---------------------------------------------------------------------------
#define PST 72
#define P12 132
#define A_SQH  0
#define A_KH0  9216
#define A_KH1  18432
#define A_V0   27648
#define A_V1   36864
#define A_E0   46080
#define A_E1   55296
#define A_E2   64512
#define A_P1A  73728
#define A_P1B  82944
#define A_P2   92160          // 16896
#define A_SPH  A_P2
#define A_STASH A_P1A
#define A_CORR 109056
#define A_SSM  109312
#define A_SSI  109568
#define A_AM0  109824
#define A_AM1  110080
#define A_IMSK 110336
#define A_TOTAL 110848

__device__ __forceinline__ int ebuf_of(int idx) {
    return (idx == 0) ? A_E0 : (idx == 1) ? A_E1 : A_E2;
}
__device__ __forceinline__ void cpa_tile64(uint32_t sb, int dstoff,
                                           const __half* src, int tid)
{
#pragma unroll
    for (int it = 0; it < 2; it++) {
        int i = tid + it * 256;
        int r = i >> 3, c = (i & 7) * 8;
        cpasync16(sb + dstoff + (r * PST + c) * 2, src + r * 64 + c);
    }
}
__device__ __forceinline__ float ldh(const char* sm, int base, int idx) {
    return __half2float(*(const __half*)(sm + base + idx * 2));
}

// QK single-term fp16: 32 MMAs.
__device__ __forceinline__ void qk_tile(float sacc[8][4], uint32_t sb,
                                        int kOff, int wm, int lane)
{
#pragma unroll
    for (int k = 0; k < 4; k++) {
        const uint32_t ko = (k * 16 + (lane >> 4) * 8) * 2;
        uint32_t aH[4];
        ldsm4(aH[0], aH[1], aH[2], aH[3],
              sb + A_SQH + (wm + (lane & 15)) * PST * 2 + ko);
#pragma unroll
        for (int nb = 0; nb < 4; nb++) {
            uint32_t bK[4];
            ldsm4(bK[0], bK[1], bK[2], bK[3],
                  sb + kOff + (nb * 16 + (lane & 15)) * PST * 2 + ko);
            mma16816h(sacc[2 * nb], aH[0], aH[1], aH[2], aH[3], bK[0], bK[2]);
            mma16816h(sacc[2 * nb + 1], aH[0], aH[1], aH[2], aH[3], bK[1], bK[3]);
        }
    }
}

// P1 full fresh chunk: 32 MMAs.
__device__ __forceinline__ void p1_full(uint32_t sb, char* sm, int ebuf,
                                        int p1buf, int m0p, int lane,
                                        int g, int t4)
{
    float pacc[8][4];
#pragma unroll
    for (int j = 0; j < 8; j++)
#pragma unroll
        for (int p = 0; p < 4; p++) pacc[j][p] = 0.f;
#pragma unroll
    for (int k = 0; k < 4; k++) {
        const uint32_t ko = (k * 16 + (lane >> 4) * 8) * 2;
        uint32_t a[4];
        ldsm4(a[0], a[1], a[2], a[3],
              sb + A_SQH + (m0p + (lane & 15)) * PST * 2 + ko);
#pragma unroll
        for (int nb = 0; nb < 4; nb++) {
            uint32_t be[4];
            ldsm4(be[0], be[1], be[2], be[3],
                  sb + ebuf + (nb * 16 + (lane & 15)) * PST * 2 + ko);
            mma16816h(pacc[2 * nb], a[0], a[1], a[2], a[3], be[0], be[2]);
            mma16816h(pacc[2 * nb + 1], a[0], a[1], a[2], a[3], be[1], be[3]);
        }
    }
#pragma unroll
    for (int j = 0; j < 8; j++) {
        int w = 8 * j + 2 * t4;
        *(uint32_t*)(sm + p1buf + ((m0p + g) * PST + w) * 2) =
            pk2h(pacc[j][0], pacc[j][1]);
        *(uint32_t*)(sm + p1buf + ((m0p + 8 + g) * PST + w) * 2) =
            pk2h(pacc[j][2], pacc[j][3]);
    }
}

// P2: K @ E^T (both chunks): 64 MMAs/warp.
__device__ __forceinline__ void p2_tile(uint32_t sb, char* sm, int kOff,
                                        int e0b, int e1b,
                                        int m0p, int lane, int g, int t4)
{
#pragma unroll
    for (int c = 0; c < 2; c++) {
        const int ebuf = c ? e1b : e0b;
        float pacc[8][4];
#pragma unroll
        for (int j = 0; j < 8; j++)
#pragma unroll
            for (int p = 0; p < 4; p++) pacc[j][p] = 0.f;
#pragma unroll
        for (int k = 0; k < 4; k++) {
            const uint32_t ko = (k * 16 + (lane >> 4) * 8) * 2;
            uint32_t a[4];
            ldsm4(a[0], a[1], a[2], a[3],
                  sb + kOff + (m0p + (lane & 15)) * PST * 2 + ko);
#pragma unroll
            for (int nb = 0; nb < 4; nb++) {
                uint32_t be[4];
                ldsm4(be[0], be[1], be[2], be[3],
                      sb + ebuf + (nb * 16 + (lane & 15)) * PST * 2 + ko);
                mma16816h(pacc[2 * nb], a[0], a[1], a[2], a[3], be[0], be[2]);
                mma16816h(pacc[2 * nb + 1], a[0], a[1], a[2], a[3], be[1], be[3]);
            }
        }
#pragma unroll
        for (int j = 0; j < 8; j++) {
            int w = c * 64 + 8 * j + 2 * t4;
            *(uint32_t*)(sm + A_P2 + ((m0p + g) * P12 + w) * 2) =
                pk2h(pacc[j][0], pacc[j][1]);
            *(uint32_t*)(sm + A_P2 + ((m0p + 8 + g) * P12 + w) * 2) =
                pk2h(pacc[j][2], pacc[j][3]);
        }
    }
}

// PV single-term fp16.
__device__ __forceinline__ void pv_tile(float cacc[4][4], uint32_t sb,
                                        int prOff, int vOff,
                                        int wm2, int wn2, int lane)
{
#pragma unroll
    for (int kk = 0; kk < 4; kk++) {
        const uint32_t ko = (kk * 16 + (lane >> 4) * 8) * 2;
        uint32_t aP[4];
        ldsm4(aP[0], aP[1], aP[2], aP[3],
              sb + prOff + (wm2 + (lane & 15)) * PST * 2 + ko);
        const uint32_t trow = (kk * 16 + (lane & 7) + 8 * ((lane >> 3) & 1)) * PST;
#pragma unroll
        for (int dh = 0; dh < 2; dh++) {
            const uint32_t tcol = wn2 + dh * 16 + ((lane >> 4) & 1) * 8;
            uint32_t v[4];
            ldsm4t(v[0], v[1], v[2], v[3], sb + vOff + (trow + tcol) * 2);
            const int nf = dh * 2;
            mma16816h(cacc[nf], aP[0], aP[1], aP[2], aP[3], v[0], v[1]);
            mma16816h(cacc[nf + 1], aP[0], aP[1], aP[2], aP[3], v[2], v[3]);
        }
    }
}

__global__ __launch_bounds__(256, 2)
void attn_mma(const float* __restrict__ amask, const float* __restrict__ imask,
              const float* __restrict__ gate, float* __restrict__ outp)
{
    extern __shared__ char sm[];
    const uint32_t sb = smem_u32(sm);
    const int tid = threadIdx.x, warp = tid >> 5, lane = tid & 31;
    const int g = lane >> 2, t4 = lane & 3;
    const int bh = blockIdx.y, b = bh >> 4, h = bh & 15;
    const int l0 = blockIdx.x * 64;
    const int wm = warp * 16;
    const int wm2 = (warp >> 1) * 16, wn2 = (warp & 1) * 32;

    // preloop: Q + tile0 (K,V,E chunk0 into E[0], E chunk1 into E[2])
    cpa_tile64(sb, A_SQH, g_Qf + ((size_t)bh * SQ + l0) * DH, tid);
    cpa_tile64(sb, A_KH0, g_Kf + ((size_t)bh * SQ) * DH, tid);
    cpa_tile64(sb, A_V0, g_Vf + ((size_t)bh * SQ) * DH, tid);
    cpa_tile64(sb, A_E0, g_Ef + (size_t)(l0 + 960) * 64, tid);
    cpa_tile64(sb, A_E2, g_Ef + (size_t)(l0 + 1024) * 64, tid);
    if (tid < 64) ((float*)(sm + A_AM0))[tid] = amask[b * SQ + tid];
    if (tid < 32)
        ((float4*)(sm + A_IMSK))[tid] = ((const float4*)(imask + b * LI))[tid];
    CP_COMMIT();

    float cacc[4][4];
#pragma unroll
    for (int i = 0; i < 4; i++)
#pragma unroll
        for (int j = 0; j < 4; j++) cacc[i][j] = 0.f;
    float mrow[2] = {-1e30f, -1e30f}, ssum[2] = {0.f, 0.f};
    float* corr_sm = (float*)(sm + A_CORR);
    const float* imsk = (const float*)(sm + A_IMSK);

    // ======================= main pass =======================
    for (int rt = 0; rt < 16; rt++) {
        const int pb = rt & 1;
        const int kbf = pb ? A_KH1 : A_KH0;
        const int vbf = pb ? A_V1 : A_V0;
        const int e0b = ebuf_of(rt % 3);
        const int e1b = ebuf_of((rt + 2) % 3);
        const int p1b = pb ? A_P1B : A_P1A;
        const int amb = pb ? A_AM1 : A_AM0;

        CP_WAIT(0);
        __syncthreads();                                     // [B1]

        // prefetch tile rt+1 into alternate buffers (hidden behind compute)
        if (rt + 1 < 16) {
            const int r1 = (rt + 1) * 64;
            cpa_tile64(sb, pb ? A_KH0 : A_KH1,
                       g_Kf + ((size_t)bh * SQ + r1) * DH, tid);
            cpa_tile64(sb, pb ? A_V0 : A_V1,
                       g_Vf + ((size_t)bh * SQ + r1) * DH, tid);
            cpa_tile64(sb, ebuf_of((rt + 1) % 3),
                       g_Ef + (size_t)(l0 - r1 + 960) * 64, tid);
            if (tid < 64)
                ((float*)(sm + (pb ? A_AM0 : A_AM1)))[tid] = amask[b * SQ + r1 + tid];
            CP_COMMIT();
        }

        // ---- compute phase ----
        float sacc[8][4];
        if (warp < 4) {
#pragma unroll
            for (int j = 0; j < 8; j++)
#pragma unroll
                for (int p = 0; p < 4; p++) sacc[j][p] = 0.f;
            qk_tile(sacc, sb, kbf, wm, lane);
            p1_full(sb, sm, e0b, p1b, wm, lane, g, t4);
            if (rt == 0)
                p1_full(sb, sm, A_E2, A_P1B, wm, lane, g, t4);
        } else {
            p2_tile(sb, sm, kbf, e0b, e1b, (warp - 4) * 16, lane, g, t4);
        }
        __syncthreads();                                     // [B2]

        // ---- softmax ----
        if (warp < 4) {
            const int l = wm + g;
            const int p1c0 = pb ? A_P1B : A_P1A;
            const int p1c1 = pb ? A_P1A : A_P1B;
            const float* amsk = (const float*)(sm + amb);
#pragma unroll
            for (int j = 0; j < 8; j++) {
                const int r = 8 * j + 2 * t4;
                const int w = l - r + 63;
                const int w1 = w - 1, w2 = w + 8, w3 = w + 7;
                float p1a  = ldh(sm, (w  >= 64) ? p1c1 : p1c0, l * PST + (w  & 63));
                float p1b_ = ldh(sm, (w1 >= 64) ? p1c1 : p1c0, l * PST + (w1 & 63));
                float p1c  = ldh(sm, (w2 >= 64) ? p1c1 : p1c0, (l + 8) * PST + (w2 & 63));
                float p1d  = ldh(sm, (w3 >= 64) ? p1c1 : p1c0, (l + 8) * PST + (w3 & 63));
                sacc[j][0] = (sacc[j][0] + p1a  + ldh(sm, A_P2, r * P12 + w)) * 0.125f + amsk[r];
                sacc[j][1] = (sacc[j][1] + p1b_ + ldh(sm, A_P2, (r + 1) * P12 + w1)) * 0.125f + amsk[r + 1];
                sacc[j][2] = (sacc[j][2] + p1c  + ldh(sm, A_P2, r * P12 + w2)) * 0.125f + amsk[r];
                sacc[j][3] = (sacc[j][3] + p1d  + ldh(sm, A_P2, (r + 1) * P12 + w3)) * 0.125f + amsk[r + 1];
            }
            float mt0 = -1e30f, mt1 = -1e30f;
#pragma unroll
            for (int j = 0; j < 8; j++) {
                mt0 = fmaxf(mt0, fmaxf(sacc[j][0], sacc[j][1]));
                mt1 = fmaxf(mt1, fmaxf(sacc[j][2], sacc[j][3]));
            }
            mt0 = fmaxf(mt0, __shfl_xor_sync(0xffffffffu, mt0, 1));
            mt0 = fmaxf(mt0, __shfl_xor_sync(0xffffffffu, mt0, 2));
            mt1 = fmaxf(mt1, __shfl_xor_sync(0xffffffffu, mt1, 1));
            mt1 = fmaxf(mt1, __shfl_xor_sync(0xffffffffu, mt1, 2));
            asm volatile("bar.sync 1, 128;" ::: "memory");   // P2 reads done
            float mn0 = fmaxf(mrow[0], mt0), mn1 = fmaxf(mrow[1], mt1);
            float cr0 = __expf(mrow[0] - mn0), cr1 = __expf(mrow[1] - mn1);
            mrow[0] = mn0; mrow[1] = mn1;
            float ps0 = 0.f, ps1 = 0.f;
#pragma unroll
            for (int j = 0; j < 8; j++) {
                float p00 = __expf(sacc[j][0] - mn0), p01 = __expf(sacc[j][1] - mn0);
                float p10 = __expf(sacc[j][2] - mn1), p11 = __expf(sacc[j][3] - mn1);
                ps0 += p00 + p01; ps1 += p10 + p11;
                int cidx = 8 * j + 2 * t4;
                *(uint32_t*)(sm + A_SPH + (l * PST + cidx) * 2) = pk2h(p00, p01);
                *(uint32_t*)(sm + A_SPH + ((l + 8) * PST + cidx) * 2) = pk2h(p10, p11);
            }
            ps0 += __shfl_xor_sync(0xffffffffu, ps0, 1);
            ps0 += __shfl_xor_sync(0xffffffffu, ps0, 2);
            ps1 += __shfl_xor_sync(0xffffffffu, ps1, 1);
            ps1 += __shfl_xor_sync(0xffffffffu, ps1, 2);
            ssum[0] = ssum[0] * cr0 + ps0;
            ssum[1] = ssum[1] * cr1 + ps1;
            if (t4 == 0) { corr_sm[l] = cr0; corr_sm[l + 8] = cr1; }
        }
        __syncthreads();                                     // [B3]

        // ---- PV ----
        {
            float c0r = corr_sm[wm2 + g], c1r = corr_sm[wm2 + 8 + g];
#pragma unroll
            for (int nf = 0; nf < 4; nf++) {
                cacc[nf][0] *= c0r; cacc[nf][1] *= c0r;
                cacc[nf][2] *= c1r; cacc[nf][3] *= c1r;
            }
            pv_tile(cacc, sb, A_SPH, vbf, wm2, wn2, lane);
        }
        // next tile's B1 provides end-of-tile ordering
    }
    __syncthreads();

    // stash main ctx + ssum, reset
    {
        float* stash = (float*)(sm + A_STASH);
#pragma unroll
        for (int nf = 0; nf < 4; nf++) {
            int d = wn2 + 8 * nf + 2 * t4;
            stash[(wm2 + g) * 68 + d] = cacc[nf][0];
            stash[(wm2 + g) * 68 + d + 1] = cacc[nf][1];
            stash[(wm2 + 8 + g) * 68 + d] = cacc[nf][2];
            stash[(wm2 + 8 + g) * 68 + d + 1] = cacc[nf][3];
            cacc[nf][0] = cacc[nf][1] = cacc[nf][2] = cacc[nf][3] = 0.f;
        }
        if (warp < 4 && t4 == 0) {
            ((float*)(sm + A_SSM))[wm + g] = ssum[0];
            ((float*)(sm + A_SSM))[wm + g + 8] = ssum[1];
        }
        mrow[0] = mrow[1] = -1e30f; ssum[0] = ssum[1] = 0.f;
    }
    __syncthreads();

    // ======================= instruct pass =======================
    for (int rt = 0; rt < 2; rt++) {
        const int r0 = rt * 64;
        cpa_tile64(sb, A_KH0, g_IKf + ((size_t)bh * LI + r0) * DH, tid);
        cpa_tile64(sb, A_V0, g_IVf + ((size_t)bh * LI + r0) * DH, tid);
        CP_COMMIT();
        CP_WAIT(0);
        __syncthreads();

        if (warp < 4) {
            float sacc[8][4];
#pragma unroll
            for (int j = 0; j < 8; j++)
#pragma unroll
                for (int p = 0; p < 4; p++) sacc[j][p] = 0.f;
            qk_tile(sacc, sb, A_KH0, wm, lane);

            const int l = wm + g;
            float mt0 = -1e30f, mt1 = -1e30f;
#pragma unroll
            for (int j = 0; j < 8; j++) {
                const int r = 8 * j + 2 * t4;
                sacc[j][0] = sacc[j][0] * 0.125f + imsk[r0 + r];
                sacc[j][1] = sacc[j][1] * 0.125f + imsk[r0 + r + 1];
                sacc[j][2] = sacc[j][2] * 0.125f + imsk[r0 + r];
                sacc[j][3] = sacc[j][3] * 0.125f + imsk[r0 + r + 1];
                mt0 = fmaxf(mt0, fmaxf(sacc[j][0], sacc[j][1]));
                mt1 = fmaxf(mt1, fmaxf(sacc[j][2], sacc[j][3]));
            }
            mt0 = fmaxf(mt0, __shfl_xor_sync(0xffffffffu, mt0, 1));
            mt0 = fmaxf(mt0, __shfl_xor_sync(0xffffffffu, mt0, 2));
            mt1 = fmaxf(mt1, __shfl_xor_sync(0xffffffffu, mt1, 1));
            mt1 = fmaxf(mt1, __shfl_xor_sync(0xffffffffu, mt1, 2));
            float mn0 = fmaxf(mrow[0], mt0), mn1 = fmaxf(mrow[1], mt1);
            float cr0 = __expf(mrow[0] - mn0), cr1 = __expf(mrow[1] - mn1);
            mrow[0] = mn0; mrow[1] = mn1;
            float ps0 = 0.f, ps1 = 0.f;
#pragma unroll
            for (int j = 0; j < 8; j++) {
                float p00 = __expf(sacc[j][0] - mn0), p01 = __expf(sacc[j][1] - mn0);
                float p10 = __expf(sacc[j][2] - mn1), p11 = __expf(sacc[j][3] - mn1);
                ps0 += p00 + p01; ps1 += p10 + p11;
                int cidx = 8 * j + 2 * t4;
                *(uint32_t*)(sm + A_SPH + (l * PST + cidx) * 2) = pk2h(p00, p01);
                *(uint32_t*)(sm + A_SPH + ((l + 8) * PST + cidx) * 2) = pk2h(p10, p11);
            }
            ps0 += __shfl_xor_sync(0xffffffffu, ps0, 1);
            ps0 += __shfl_xor_sync(0xffffffffu, ps0, 2);
            ps1 += __shfl_xor_sync(0xffffffffu, ps1, 1);
            ps1 += __shfl_xor_sync(0xffffffffu, ps1, 2);
            ssum[0] = ssum[0] * cr0 + ps0;
            ssum[1] = ssum[1] * cr1 + ps1;
            if (t4 == 0) { corr_sm[l] = cr0; corr_sm[l + 8] = cr1; }
        }
        __syncthreads();

        {
            float c0r = corr_sm[wm2 + g], c1r = corr_sm[wm2 + 8 + g];
#pragma unroll
            for (int nf = 0; nf < 4; nf++) {
                cacc[nf][0] *= c0r; cacc[nf][1] *= c0r;
                cacc[nf][2] *= c1r; cacc[nf][3] *= c1r;
            }
            pv_tile(cacc, sb, A_SPH, A_V0, wm2, wn2, lane);
        }
        __syncthreads();
    }

    if (warp < 4 && t4 == 0) {
        ((float*)(sm + A_SSI))[wm + g] = ssum[0];
        ((float*)(sm + A_SSI))[wm + g + 8] = ssum[1];
    }
    __syncthreads();

    {
        const float tg = tanhf(gate[h]);
        const float* stash = (const float*)(sm + A_STASH);
        const float* ssmv = (const float*)(sm + A_SSM);
        const float* ssiv = (const float*)(sm + A_SSI);
        const float rnm0 = 1.f / ssmv[wm2 + g], rni0 = tg / ssiv[wm2 + g];
        const float rnm1 = 1.f / ssmv[wm2 + 8 + g], rni1 = tg / ssiv[wm2 + 8 + g];
#pragma unroll
        for (int nf = 0; nf < 4; nf++) {
            const int d = wn2 + 8 * nf + 2 * t4;
            float2 o0, o1;
            o0.x = stash[(wm2 + g) * 68 + d] * rnm0 + cacc[nf][0] * rni0;
            o0.y = stash[(wm2 + g) * 68 + d + 1] * rnm0 + cacc[nf][1] * rni0;
            o1.x = stash[(wm2 + 8 + g) * 68 + d] * rnm1 + cacc[nf][2] * rni1;
            o1.y = stash[(wm2 + 8 + g) * 68 + d + 1] * rnm1 + cacc[nf][3] * rni1;
            *(float2*)(outp + ((size_t)(b * SQ + l0 + wm2 + g)) * HIDDEN + h * DH + d) = o0;
            *(float2*)(outp + ((size_t)(b * SQ + l0 + wm2 + 8 + g)) * HIDDEN + h * DH + d) = o1;
        }
    }
}

// ---------------------------------------------------------------------------
extern "C" void kernel_launch(void* const* d_in, const int* in_sizes, int n_in,
                              void* d_out, int out_size)
{
    (void)in_sizes; (void)n_in; (void)out_size;
    const float* hs    = (const float*)d_in[0];
    const float* amask = (const float*)d_in[1];
    const float* ihs   = (const float*)d_in[2];
    const float* imask = (const float*)d_in[3];
    const float* Wq    = (const float*)d_in[4];
    const float* bq    = (const float*)d_in[5];
    const float* Wk    = (const float*)d_in[6];
    const float* bk    = (const float*)d_in[7];
    const float* Wv    = (const float*)d_in[8];
    const float* bv    = (const float*)d_in[9];
    const float* gate  = (const float*)d_in[10];
    const float* dist  = (const float*)d_in[11];
    float* out = (float*)d_out;

    __half *qf, *kf, *vf, *ikf, *ivf, *ef, *xc, *ixc, *wc;
    cudaGetSymbolAddress((void**)&qf, g_Qf);
    cudaGetSymbolAddress((void**)&kf, g_Kf);
    cudaGetSymbolAddress((void**)&vf, g_Vf);
    cudaGetSymbolAddress((void**)&ikf, g_IKf);
    cudaGetSymbolAddress((void**)&ivf, g_IVf);
    cudaGetSymbolAddress((void**)&ef, g_Ef);
    cudaGetSymbolAddress((void**)&xc, g_Xh);
    cudaGetSymbolAddress((void**)&ixc, g_IXh);
    cudaGetSymbolAddress((void**)&wc, g_Wh);

    cudaFuncSetAttribute(gemm_mma, cudaFuncAttributeMaxDynamicSharedMemorySize, GEMM_SMEM);
    cudaFuncSetAttribute(attn_mma, cudaFuncAttributeMaxDynamicSharedMemorySize, A_TOTAL);

    conv_all<<<NX_BASE3 + NX_W, 256>>>((const float4*)hs, xc,
                                       (const float4*)ihs, ixc, dist, ef,
                                       Wq, Wk, Wv, wc);

    gemm_mma<<<416, 256, GEMM_SMEM>>>(xc, ixc, wc, bq, bk, bv,
                                      qf, kf, vf, ikf, ivf);

    attn_mma<<<dim3(SQ / 64, BHN), 256, A_TOTAL>>>(amask, imask, gate, out);
}

// round 17
// speedup vs baseline: 1.0151x; 1.0151x over previous
#include <cuda_runtime.h>
#include <cuda_bf16.h>
#include <cuda_fp16.h>
#include <math.h>
#include <cstdint>

#define NB 4
#define NH 16
#define DH 64
#define SQ 1024
#define LI 128
#define HIDDEN 1024
#define BHN (NB * NH)

// ---------------- scratch (all fp16, single-term) ---------------------------
__device__ __align__(16) __half g_Qf[BHN * SQ * DH];
__device__ __align__(16) __half g_Kf[BHN * SQ * DH];
__device__ __align__(16) __half g_Vf[BHN * SQ * DH];
__device__ __align__(16) __half g_IKf[BHN * LI * DH];
__device__ __align__(16) __half g_IVf[BHN * LI * DH];
__device__ __align__(16) __half g_Ef[2048 * DH];

__device__ __align__(16) __half g_Xh[NB * SQ * HIDDEN];
__device__ __align__(16) __half g_IXh[NB * LI * HIDDEN];
__device__ __align__(16) __half g_Wh[3 * HIDDEN * HIDDEN];   // [n(3072)][k(1024)]

// ---------------- helpers ---------------------------------------------------
__device__ __forceinline__ uint32_t smem_u32(const void* p) {
    uint32_t a;
    asm("{ .reg .u64 t; cvta.to.shared.u64 t, %1; cvt.u32.u64 %0, t; }" : "=r"(a) : "l"(p));
    return a;
}
__device__ __forceinline__ void ldsm4(uint32_t& r0, uint32_t& r1, uint32_t& r2,
                                      uint32_t& r3, uint32_t addr) {
    asm volatile("ldmatrix.sync.aligned.m8n8.x4.shared.b16 {%0,%1,%2,%3}, [%4];"
                 : "=r"(r0), "=r"(r1), "=r"(r2), "=r"(r3) : "r"(addr));
}
__device__ __forceinline__ void ldsm4t(uint32_t& r0, uint32_t& r1, uint32_t& r2,
                                       uint32_t& r3, uint32_t addr) {
    asm volatile("ldmatrix.sync.aligned.m8n8.x4.trans.shared.b16 {%0,%1,%2,%3}, [%4];"
                 : "=r"(r0), "=r"(r1), "=r"(r2), "=r"(r3) : "r"(addr));
}
__device__ __forceinline__ void mma16816h(float* c, uint32_t a0, uint32_t a1,
                                          uint32_t a2, uint32_t a3,
                                          uint32_t b0, uint32_t b1) {
    asm volatile(
        "mma.sync.aligned.m16n8k16.row.col.f32.f16.f16.f32 "
        "{%0,%1,%2,%3}, {%4,%5,%6,%7}, {%8,%9}, {%0,%1,%2,%3};"
        : "+f"(c[0]), "+f"(c[1]), "+f"(c[2]), "+f"(c[3])
        : "r"(a0), "r"(a1), "r"(a2), "r"(a3), "r"(b0), "r"(b1));
}
__device__ __forceinline__ uint32_t pk2h(float a, float b) {
    __half2 t = __floats2half2_rn(a, b);
    return *(uint32_t*)&t;
}
__device__ __forceinline__ void cpasync16(uint32_t dst, const void* src) {
    asm volatile("cp.async.cg.shared.global [%0], [%1], 16;" :: "r"(dst), "l"(src));
}
#define CP_COMMIT() asm volatile("cp.async.commit_group;" ::: "memory")
#define CP_WAIT(n)  asm volatile("cp.async.wait_group %0;" :: "n"(n) : "memory")

// ---------------------------------------------------------------------------
// Conversions: X / X-instruct / E / W merged (single-term fp16 everywhere).
// ---------------------------------------------------------------------------
#define NX_MAIN (NB * SQ * HIDDEN / 4 / 256)
#define NX_INST (NB * LI * HIDDEN / 4 / 256)
#define NX_E    (2048 * 64 / 256)
#define NX_W    3072
#define NX_BASE3 (NX_MAIN + NX_INST + NX_E)

__global__ __launch_bounds__(256)
void conv_all(const float4* __restrict__ xm, __half* __restrict__ dm,
              const float4* __restrict__ xi, __half* __restrict__ di,
              const float* __restrict__ dist, __half* __restrict__ eh,
              const float* __restrict__ Wq, const float* __restrict__ Wk,
              const float* __restrict__ Wv, __half* __restrict__ wdst)
{
    __shared__ float t[32][33];
    int blk = blockIdx.x;
    if (blk >= NX_BASE3) {
        int wblk = blk - NX_BASE3;
        int z = wblk >> 10, rem = wblk & 1023;
        int bx = rem & 31, by = rem >> 5;
        const float* W = (z == 0) ? Wq : (z == 1) ? Wk : Wv;
        int tx = threadIdx.x & 31, ty = threadIdx.x >> 5;
        int n = bx * 32 + tx, k0 = by * 32;
#pragma unroll
        for (int j = 0; j < 4; j++)
            t[ty + 8 * j][tx] = W[(size_t)(k0 + ty + 8 * j) * HIDDEN + n];
        __syncthreads();
        size_t nrow = (size_t)z * HIDDEN + bx * 32;
#pragma unroll
        for (int j = 0; j < 4; j++)
            wdst[(nrow + ty + 8 * j) * HIDDEN + k0 + tx] = __float2half(t[tx][ty + 8 * j]);
        return;
    }
    if (blk >= NX_MAIN + NX_INST) {
        int i = (blk - NX_MAIN - NX_INST) * 256 + threadIdx.x;
        float v = (i < 2047 * 64) ? dist[i] : 0.f;
        eh[i] = __float2half(v);
        return;
    }
    const float4* src = (blk < NX_MAIN) ? xm : xi;
    __half* dst = (blk < NX_MAIN) ? dm : di;
    int i = ((blk < NX_MAIN) ? blk : blk - NX_MAIN) * 256 + threadIdx.x;
    float4 v = src[i];
    uint2 H;
    H.x = pk2h(v.x, v.y);
    H.y = pk2h(v.z, v.w);
    *(uint2*)(dst + (size_t)i * 4) = H;
}

// ---------------------------------------------------------------------------
// Merged projection GEMM: K=1024 fp16, all outputs single fp16.
// Barrier diet: prefetch moved after top sync -> bottom sync removed.
// ---------------------------------------------------------------------------
#define AST 72
#define TA (128 * AST * 2)
#define TB (256 * AST * 2)
#define GEMM_SMEM (2 * (TA + TB))

__global__ __launch_bounds__(256, 1)
void gemm_mma(const __half* __restrict__ Am, const __half* __restrict__ Ai,
              const __half* __restrict__ Bm,
              const float* __restrict__ bq, const float* __restrict__ bk,
              const float* __restrict__ bv,
              __half* oQf, __half* oKf, __half* oVf,
              __half* oIKf, __half* oIVf)
{
    extern __shared__ char smem[];
    const uint32_t sb = smem_u32(smem);
    const int tid = threadIdx.x, warp = tid >> 5, lane = tid & 31;

    const __half* A;
    int msh, Slen, m0, n0g, inst;
    {
        int blk = blockIdx.x;
        if (blk < 384) {
            A = Am; msh = 10; Slen = SQ; inst = 0;
            m0 = (blk / 12) * 128; n0g = (blk % 12) * 256;
        } else {
            blk -= 384;
            A = Ai; msh = 7; Slen = LI; inst = 1;
            m0 = (blk / 8) * 128; n0g = 1024 + (blk % 8) * 256;
        }
    }
    const int wm = (warp >> 2) * 64, wn = (warp & 3) * 64;

    const int cr = tid >> 3, cko = (tid & 7) * 8;
    const __half* Ag = A + (size_t)(m0 + cr) * HIDDEN + cko;
    const __half* Bg = Bm + (size_t)(n0g + cr) * HIDDEN + cko;
    const uint32_t sAo = (cr * AST + cko) * 2;

    float acc[4][8][4];
#pragma unroll
    for (int i = 0; i < 4; i++)
#pragma unroll
        for (int j = 0; j < 8; j++)
#pragma unroll
            for (int p = 0; p < 4; p++) acc[i][j][p] = 0.f;

#pragma unroll
    for (int i = 0; i < 4; i++)
        cpasync16(sb + sAo + i * 32 * AST * 2, Ag + (size_t)(i * 32) * HIDDEN);
#pragma unroll
    for (int i = 0; i < 8; i++)
        cpasync16(sb + TA + sAo + i * 32 * AST * 2, Bg + (size_t)(i * 32) * HIDDEN);
    CP_COMMIT();

    const int NCH = 16;
    for (int c = 0; c < NCH; c++) {
        const int p = c & 1;
        CP_WAIT(0);
        __syncthreads();
        if (c + 1 < NCH) {
            const int pn = (c + 1) & 1;
            const int koff = (c + 1) * 64;
#pragma unroll
            for (int i = 0; i < 4; i++)
                cpasync16(sb + pn * (TA + TB) + sAo + i * 32 * AST * 2,
                          Ag + (size_t)(i * 32) * HIDDEN + koff);
#pragma unroll
            for (int i = 0; i < 8; i++)
                cpasync16(sb + pn * (TA + TB) + TA + sAo + i * 32 * AST * 2,
                          Bg + (size_t)(i * 32) * HIDDEN + koff);
            CP_COMMIT();
        }

        const uint32_t aw = sb + p * (TA + TB) +
                            ((wm + (lane & 15)) * AST + (lane >> 4) * 8) * 2;
        const uint32_t bw = sb + p * (TA + TB) + TA +
                            ((wn + (lane & 15)) * AST + (lane >> 4) * 8) * 2;
#pragma unroll
        for (int k16 = 0; k16 < 4; k16++) {
            const uint32_t ko = k16 * 32;
            uint32_t a[4][4], b[4][4];
#pragma unroll
            for (int mt = 0; mt < 4; mt++)
                ldsm4(a[mt][0], a[mt][1], a[mt][2], a[mt][3],
                      aw + mt * 16 * AST * 2 + ko);
#pragma unroll
            for (int nb = 0; nb < 4; nb++)
                ldsm4(b[nb][0], b[nb][1], b[nb][2], b[nb][3],
                      bw + nb * 16 * AST * 2 + ko);
#pragma unroll
            for (int mt = 0; mt < 4; mt++)
#pragma unroll
                for (int nb = 0; nb < 4; nb++) {
                    mma16816h(acc[mt][2 * nb], a[mt][0], a[mt][1], a[mt][2], a[mt][3],
                              b[nb][0], b[nb][2]);
                    mma16816h(acc[mt][2 * nb + 1], a[mt][0], a[mt][1], a[mt][2], a[mt][3],
                              b[nb][1], b[nb][3]);
                }
        }
    }

#pragma unroll
    for (int nt = 0; nt < 8; nt++) {
        const int n = n0g + wn + nt * 8 + (lane & 3) * 2;
        const int wsel = n >> 10, nn = n & 1023;
        const float* bias = (wsel == 0) ? bq : (wsel == 1) ? bk : bv;
        const float b0 = bias[nn], b1 = bias[nn + 1];
        const size_t hoff = ((size_t)(nn >> 6)) * Slen;
        const int d = nn & 63;
        __half* pv = inst ? ((wsel == 1) ? oIKf : oIVf)
                          : ((wsel == 0) ? oQf : (wsel == 1) ? oKf : oVf);
#pragma unroll
        for (int mt = 0; mt < 4; mt++)
#pragma unroll
            for (int half = 0; half < 2; half++) {
                const int r = m0 + wm + mt * 16 + (lane >> 2) + half * 8;
                const int bb = r >> msh, t = r - (bb << msh);
                float vx = acc[mt][nt][half * 2 + 0] + b0;
                float vy = acc[mt][nt][half * 2 + 1] + b1;
                size_t off = ((size_t)bb * NH * Slen + hoff + t) * DH + d;
                *(uint32_t*)(pv + off) = pk2h(vx, vy);
            }
    }
}

// ---------------------------------------------------------------------------
// Attention v9: v6 base + fused QK/P1 k-loop (shared Q fragments) + separate
// probs buffer (partial bar deleted). 92 KB smem, 2 CTAs/SM.
// ---------------------------------------------------------------------------
#define PST 72
#define P12 132
#define A_SQH  0
#define A_KH   9216
#define A_VH   18432
#define A_E0   27648
#define A_E1   36864
#define A_P1A  46080
#define A_P1B  55296
#define A_P2   64512          // 16896
#define A_PR   81408          // probs fp16 (own buffer)
#define A_STASH A_P1A
#define A_CORR 90624
#define A_SSM  90880
#define A_SSI  91136
#define A_AMSK 91392
#define A_IMSK 91648
#define A_TOTAL 92160

__device__ __forceinline__ void cpa_tile64(uint32_t sb, int dstoff,
                                           const __half* src, int tid)
{
#pragma unroll
    for (int it = 0; it < 2; it++) {
        int i = tid + it * 256;
        int r = i >> 3, c = (i & 7) * 8;
        cpasync16(sb + dstoff + (r * PST + c) * 2, src + r * 64 + c);
    }
}
__device__ __forceinline__ float ldh(const char* sm, int base, int idx) {
    return __half2float(*(const __half*)(sm + base + idx * 2));
}

// Fused QK + P1-fresh: shares Q fragments across both GEMMs. 64 MMAs.
__device__ __forceinline__ void qkp1_tile(float sacc[8][4], uint32_t sb,
                                          char* sm, int ebuf, int p1buf,
                                          int wm, int lane, int g, int t4)
{
    float pacc[8][4];
#pragma unroll
    for (int j = 0; j < 8; j++)
#pragma unroll
        for (int p = 0; p < 4; p++) pacc[j][p] = 0.f;
#pragma unroll
    for (int k = 0; k < 4; k++) {
        const uint32_t ko = (k * 16 + (lane >> 4) * 8) * 2;
        uint32_t aH[4];
        ldsm4(aH[0], aH[1], aH[2], aH[3],
              sb + A_SQH + (wm + (lane & 15)) * PST * 2 + ko);
#pragma unroll
        for (int nb = 0; nb < 4; nb++) {
            uint32_t bK[4];
            ldsm4(bK[0], bK[1], bK[2], bK[3],
                  sb + A_KH + (nb * 16 + (lane & 15)) * PST * 2 + ko);
            mma16816h(sacc[2 * nb], aH[0], aH[1], aH[2], aH[3], bK[0], bK[2]);
            mma16816h(sacc[2 * nb + 1], aH[0], aH[1], aH[2], aH[3], bK[1], bK[3]);
        }
#pragma unroll
        for (int nb = 0; nb < 4; nb++) {
            uint32_t be[4];
            ldsm4(be[0], be[1], be[2], be[3],
                  sb + ebuf + (nb * 16 + (lane & 15)) * PST * 2 + ko);
            mma16816h(pacc[2 * nb], aH[0], aH[1], aH[2], aH[3], be[0], be[2]);
            mma16816h(pacc[2 * nb + 1], aH[0], aH[1], aH[2], aH[3], be[1], be[3]);
        }
    }
#pragma unroll
    for (int j = 0; j < 8; j++) {
        int w = 8 * j + 2 * t4;
        *(uint32_t*)(sm + p1buf + ((wm + g) * PST + w) * 2) =
            pk2h(pacc[j][0], pacc[j][1]);
        *(uint32_t*)(sm + p1buf + ((wm + 8 + g) * PST + w) * 2) =
            pk2h(pacc[j][2], pacc[j][3]);
    }
}

// QK-only (instruct pass): 32 MMAs.
__device__ __forceinline__ void qk_tile(float sacc[8][4], uint32_t sb,
                                        int wm, int lane)
{
#pragma unroll
    for (int k = 0; k < 4; k++) {
        const uint32_t ko = (k * 16 + (lane >> 4) * 8) * 2;
        uint32_t aH[4];
        ldsm4(aH[0], aH[1], aH[2], aH[3],
              sb + A_SQH + (wm + (lane & 15)) * PST * 2 + ko);
#pragma unroll
        for (int nb = 0; nb < 4; nb++) {
            uint32_t bK[4];
            ldsm4(bK[0], bK[1], bK[2], bK[3],
                  sb + A_KH + (nb * 16 + (lane & 15)) * PST * 2 + ko);
            mma16816h(sacc[2 * nb], aH[0], aH[1], aH[2], aH[3], bK[0], bK[2]);
            mma16816h(sacc[2 * nb + 1], aH[0], aH[1], aH[2], aH[3], bK[1], bK[3]);
        }
    }
}

// P1 full fresh chunk (rt==0 chunk1 init): 32 MMAs.
__device__ __forceinline__ void p1_full(uint32_t sb, char* sm, int ebuf,
                                        int p1buf, int m0p, int lane,
                                        int g, int t4)
{
    float pacc[8][4];
#pragma unroll
    for (int j = 0; j < 8; j++)
#pragma unroll
        for (int p = 0; p < 4; p++) pacc[j][p] = 0.f;
#pragma unroll
    for (int k = 0; k < 4; k++) {
        const uint32_t ko = (k * 16 + (lane >> 4) * 8) * 2;
        uint32_t a[4];
        ldsm4(a[0], a[1], a[2], a[3],
              sb + A_SQH + (m0p + (lane & 15)) * PST * 2 + ko);
#pragma unroll
        for (int nb = 0; nb < 4; nb++) {
            uint32_t be[4];
            ldsm4(be[0], be[1], be[2], be[3],
                  sb + ebuf + (nb * 16 + (lane & 15)) * PST * 2 + ko);
            mma16816h(pacc[2 * nb], a[0], a[1], a[2], a[3], be[0], be[2]);
            mma16816h(pacc[2 * nb + 1], a[0], a[1], a[2], a[3], be[1], be[3]);
        }
    }
#pragma unroll
    for (int j = 0; j < 8; j++) {
        int w = 8 * j + 2 * t4;
        *(uint32_t*)(sm + p1buf + ((m0p + g) * PST + w) * 2) =
            pk2h(pacc[j][0], pacc[j][1]);
        *(uint32_t*)(sm + p1buf + ((m0p + 8 + g) * PST + w) * 2) =
            pk2h(pacc[j][2], pacc[j][3]);
    }
}

// P2: K @ E^T (both chunks): 64 MMAs/warp.
__device__ __forceinline__ void p2_tile(uint32_t sb, char* sm, int rt,
                                        int m0p, int lane, int g, int t4)
{
#pragma unroll
    for (int c = 0; c < 2; c++) {
        const int ebuf = ((rt + c) & 1) ? A_E1 : A_E0;
        float pacc[8][4];
#pragma unroll
        for (int j = 0; j < 8; j++)
#pragma unroll
            for (int p = 0; p < 4; p++) pacc[j][p] = 0.f;
#pragma unroll
        for (int k = 0; k < 4; k++) {
            const uint32_t ko = (k * 16 + (lane >> 4) * 8) * 2;
            uint32_t a[4];
            ldsm4(a[0], a[1], a[2], a[3],
                  sb + A_KH + (m0p + (lane & 15)) * PST * 2 + ko);
#pragma unroll
            for (int nb = 0; nb < 4; nb++) {
                uint32_t be[4];
                ldsm4(be[0], be[1], be[2], be[3],
                      sb + ebuf + (nb * 16 + (lane & 15)) * PST * 2 + ko);
                mma16816h(pacc[2 * nb], a[0], a[1], a[2], a[3], be[0], be[2]);
                mma16816h(pacc[2 * nb + 1], a[0], a[1], a[2], a[3], be[1], be[3]);
            }
        }
#pragma unroll
        for (int j = 0; j < 8; j++) {
            int w = c * 64 + 8 * j + 2 * t4;
            *(uint32_t*)(sm + A_P2 + ((m0p + g) * P12 + w) * 2) =
                pk2h(pacc[j][0], pacc[j][1]);
            *(uint32_t*)(sm + A_P2 + ((m0p + 8 + g) * P12 + w) * 2) =
                pk2h(pacc[j][2], pacc[j][3]);
        }
    }
}

// PV single-term fp16 (probs from A_PR).
__device__ __forceinline__ void pv_tile(float cacc[4][4], uint32_t sb,
                                        int wm2, int wn2, int lane)
{
#pragma unroll
    for (int kk = 0; kk < 4; kk++) {
        const uint32_t ko = (kk * 16 + (lane >> 4) * 8) * 2;
        uint32_t aP[4];
        ldsm4(aP[0], aP[1], aP[2], aP[3],
              sb + A_PR + (wm2 + (lane & 15)) * PST * 2 + ko);
        const uint32_t trow = (kk * 16 + (lane & 7) + 8 * ((lane >> 3) & 1)) * PST;
#pragma unroll
        for (int dh = 0; dh < 2; dh++) {
            const uint32_t tcol = wn2 + dh * 16 + ((lane >> 4) & 1) * 8;
            uint32_t v[4];
            ldsm4t(v[0], v[1], v[2], v[3], sb + A_VH + (trow + tcol) * 2);
            const int nf = dh * 2;
            mma16816h(cacc[nf], aP[0], aP[1], aP[2], aP[3], v[0], v[1]);
            mma16816h(cacc[nf + 1], aP[0], aP[1], aP[2], aP[3], v[2], v[3]);
        }
    }
}

__global__ __launch_bounds__(256, 2)
void attn_mma(const float* __restrict__ amask, const float* __restrict__ imask,
              const float* __restrict__ gate, float* __restrict__ outp)
{
    extern __shared__ char sm[];
    const uint32_t sb = smem_u32(sm);
    const int tid = threadIdx.x, warp = tid >> 5, lane = tid & 31;
    const int g = lane >> 2, t4 = lane & 3;
    const int bh = blockIdx.y, b = bh >> 4, h = bh & 15;
    const int l0 = blockIdx.x * 64;
    const int wm = warp * 16;
    const int wm2 = (warp >> 1) * 16, wn2 = (warp & 1) * 32;

    cpa_tile64(sb, A_SQH, g_Qf + ((size_t)bh * SQ + l0) * DH, tid);
    if (tid < 32)
        ((float4*)(sm + A_IMSK))[tid] = ((const float4*)(imask + b * LI))[tid];

    float cacc[4][4];
#pragma unroll
    for (int i = 0; i < 4; i++)
#pragma unroll
        for (int j = 0; j < 4; j++) cacc[i][j] = 0.f;
    float mrow[2] = {-1e30f, -1e30f}, ssum[2] = {0.f, 0.f};
    float* corr_sm = (float*)(sm + A_CORR);
    const float* amsk = (const float*)(sm + A_AMSK);
    const float* imsk = (const float*)(sm + A_IMSK);

    // ======================= main pass =======================
    for (int rt = 0; rt < 16; rt++) {
        const int r0 = rt * 64;
        const int epb = (rt & 1) ? A_E1 : A_E0;
        const int p1b = (rt & 1) ? A_P1B : A_P1A;

        cpa_tile64(sb, A_KH, g_Kf + ((size_t)bh * SQ + r0) * DH, tid);
        cpa_tile64(sb, A_VH, g_Vf + ((size_t)bh * SQ + r0) * DH, tid);
        cpa_tile64(sb, epb, g_Ef + (size_t)(l0 - r0 + 960) * 64, tid);
        if (rt == 0)
            cpa_tile64(sb, A_E1, g_Ef + (size_t)(l0 + 1024) * 64, tid);
        if (tid < 64) ((float*)(sm + A_AMSK))[tid] = amask[b * SQ + r0 + tid];
        CP_COMMIT();
        CP_WAIT(0);
        __syncthreads();                                     // [B1]

        float sacc[8][4];
        if (warp < 4) {
#pragma unroll
            for (int j = 0; j < 8; j++)
#pragma unroll
                for (int p = 0; p < 4; p++) sacc[j][p] = 0.f;
            qkp1_tile(sacc, sb, sm, epb, p1b, wm, lane, g, t4);
            if (rt == 0)
                p1_full(sb, sm, A_E1, A_P1B, wm, lane, g, t4);
        } else {
            p2_tile(sb, sm, rt, (warp - 4) * 16, lane, g, t4);
        }
        __syncthreads();                                     // [B2]

        if (warp < 4) {
            const int l = wm + g;
            const int p1c0 = (rt & 1) ? A_P1B : A_P1A;
            const int p1c1 = (rt & 1) ? A_P1A : A_P1B;
#pragma unroll
            for (int j = 0; j < 8; j++) {
                const int r = 8 * j + 2 * t4;
                const int w = l - r + 63;
                const int w1 = w - 1, w2 = w + 8, w3 = w + 7;
                float p1a  = ldh(sm, (w  >= 64) ? p1c1 : p1c0, l * PST + (w  & 63));
                float p1b_ = ldh(sm, (w1 >= 64) ? p1c1 : p1c0, l * PST + (w1 & 63));
                float p1c  = ldh(sm, (w2 >= 64) ? p1c1 : p1c0, (l + 8) * PST + (w2 & 63));
                float p1d  = ldh(sm, (w3 >= 64) ? p1c1 : p1c0, (l + 8) * PST + (w3 & 63));
                sacc[j][0] = (sacc[j][0] + p1a  + ldh(sm, A_P2, r * P12 + w)) * 0.125f + amsk[r];
                sacc[j][1] = (sacc[j][1] + p1b_ + ldh(sm, A_P2, (r + 1) * P12 + w1)) * 0.125f + amsk[r + 1];
                sacc[j][2] = (sacc[j][2] + p1c  + ldh(sm, A_P2, r * P12 + w2)) * 0.125f + amsk[r];
                sacc[j][3] = (sacc[j][3] + p1d  + ldh(sm, A_P2, (r + 1) * P12 + w3)) * 0.125f + amsk[r + 1];
            }
            float mt0 = -1e30f, mt1 = -1e30f;
#pragma unroll
            for (int j = 0; j < 8; j++) {
                mt0 = fmaxf(mt0, fmaxf(sacc[j][0], sacc[j][1]));
                mt1 = fmaxf(mt1, fmaxf(sacc[j][2], sacc[j][3]));
            }
            mt0 = fmaxf(mt0, __shfl_xor_sync(0xffffffffu, mt0, 1));
            mt0 = fmaxf(mt0, __shfl_xor_sync(0xffffffffu, mt0, 2));
            mt1 = fmaxf(mt1, __shfl_xor_sync(0xffffffffu, mt1, 1));
            mt1 = fmaxf(mt1, __shfl_xor_sync(0xffffffffu, mt1, 2));
            float mn0 = fmaxf(mrow[0], mt0), mn1 = fmaxf(mrow[1], mt1);
            float cr0 = __expf(mrow[0] - mn0), cr1 = __expf(mrow[1] - mn1);
            mrow[0] = mn0; mrow[1] = mn1;
            float ps0 = 0.f, ps1 = 0.f;
#pragma unroll
            for (int j = 0; j < 8; j++) {
                float p00 = __expf(sacc[j][0] - mn0), p01 = __expf(sacc[j][1] - mn0);
                float p10 = __expf(sacc[j][2] - mn1), p11 = __expf(sacc[j][3] - mn1);
                ps0 += p00 + p01; ps1 += p10 + p11;
                int cidx = 8 * j + 2 * t4;
                *(uint32_t*)(sm + A_PR + (l * PST + cidx) * 2) = pk2h(p00, p01);
                *(uint32_t*)(sm + A_PR + ((l + 8) * PST + cidx) * 2) = pk2h(p10, p11);
            }
            ps0 += __shfl_xor_sync(0xffffffffu, ps0, 1);
            ps0 += __shfl_xor_sync(0xffffffffu, ps0, 2);
            ps1 += __shfl_xor_sync(0xffffffffu, ps1, 1);
            ps1 += __shfl_xor_sync(0xffffffffu, ps1, 2);
            ssum[0] = ssum[0] * cr0 + ps0;
            ssum[1] = ssum[1] * cr1 + ps1;
            if (t4 == 0) { corr_sm[l] = cr0; corr_sm[l + 8] = cr1; }
        }
        __syncthreads();                                     // [B3]

        {
            float c0r = corr_sm[wm2 + g], c1r = corr_sm[wm2 + 8 + g];
#pragma unroll
            for (int nf = 0; nf < 4; nf++) {
                cacc[nf][0] *= c0r; cacc[nf][1] *= c0r;
                cacc[nf][2] *= c1r; cacc[nf][3] *= c1r;
            }
            pv_tile(cacc, sb, wm2, wn2, lane);
        }
        __syncthreads();                                     // [B4]
    }

    // stash main ctx + ssum, reset
    {
        float* stash = (float*)(sm + A_STASH);
#pragma unroll
        for (int nf = 0; nf < 4; nf++) {
            int d = wn2 + 8 * nf + 2 * t4;
            stash[(wm2 + g) * 68 + d] = cacc[nf][0];
            stash[(wm2 + g) * 68 + d + 1] = cacc[nf][1];
            stash[(wm2 + 8 + g) * 68 + d] = cacc[nf][2];
            stash[(wm2 + 8 + g) * 68 + d + 1] = cacc[nf][3];
            cacc[nf][0] = cacc[nf][1] = cacc[nf][2] = cacc[nf][3] = 0.f;
        }
        if (warp < 4 && t4 == 0) {
            ((float*)(sm + A_SSM))[wm + g] = ssum[0];
            ((float*)(sm + A_SSM))[wm + g + 8] = ssum[1];
        }
        mrow[0] = mrow[1] = -1e30f; ssum[0] = ssum[1] = 0.f;
    }
    __syncthreads();

    // ======================= instruct pass =======================
    for (int rt = 0; rt < 2; rt++) {
        const int r0 = rt * 64;
        cpa_tile64(sb, A_KH, g_IKf + ((size_t)bh * LI + r0) * DH, tid);
        cpa_tile64(sb, A_VH, g_IVf + ((size_t)bh * LI + r0) * DH, tid);
        CP_COMMIT();
        CP_WAIT(0);
        __syncthreads();

        if (warp < 4) {
            float sacc[8][4];
#pragma unroll
            for (int j = 0; j < 8; j++)
#pragma unroll
                for (int p = 0; p < 4; p++) sacc[j][p] = 0.f;
            qk_tile(sacc, sb, wm, lane);

            const int l = wm + g;
            float mt0 = -1e30f, mt1 = -1e30f;
#pragma unroll
            for (int j = 0; j < 8; j++) {
                const int r = 8 * j + 2 * t4;
                sacc[j][0] = sacc[j][0] * 0.125f + imsk[r0 + r];
                sacc[j][1] = sacc[j][1] * 0.125f + imsk[r0 + r + 1];
                sacc[j][2] = sacc[j][2] * 0.125f + imsk[r0 + r];
                sacc[j][3] = sacc[j][3] * 0.125f + imsk[r0 + r + 1];
                mt0 = fmaxf(mt0, fmaxf(sacc[j][0], sacc[j][1]));
                mt1 = fmaxf(mt1, fmaxf(sacc[j][2], sacc[j][3]));
            }
            mt0 = fmaxf(mt0, __shfl_xor_sync(0xffffffffu, mt0, 1));
            mt0 = fmaxf(mt0, __shfl_xor_sync(0xffffffffu, mt0, 2));
            mt1 = fmaxf(mt1, __shfl_xor_sync(0xffffffffu, mt1, 1));
            mt1 = fmaxf(mt1, __shfl_xor_sync(0xffffffffu, mt1, 2));
            float mn0 = fmaxf(mrow[0], mt0), mn1 = fmaxf(mrow[1], mt1);
            float cr0 = __expf(mrow[0] - mn0), cr1 = __expf(mrow[1] - mn1);
            mrow[0] = mn0; mrow[1] = mn1;
            float ps0 = 0.f, ps1 = 0.f;
#pragma unroll
            for (int j = 0; j < 8; j++) {
                float p00 = __expf(sacc[j][0] - mn0), p01 = __expf(sacc[j][1] - mn0);
                float p10 = __expf(sacc[j][2] - mn1), p11 = __expf(sacc[j][3] - mn1);
                ps0 += p00 + p01; ps1 += p10 + p11;
                int cidx = 8 * j + 2 * t4;
                *(uint32_t*)(sm + A_PR + (l * PST + cidx) * 2) = pk2h(p00, p01);
                *(uint32_t*)(sm + A_PR + ((l + 8) * PST + cidx) * 2) = pk2h(p10, p11);
            }
            ps0 += __shfl_xor_sync(0xffffffffu, ps0, 1);
            ps0 += __shfl_xor_sync(0xffffffffu, ps0, 2);
            ps1 += __shfl_xor_sync(0xffffffffu, ps1, 1);
            ps1 += __shfl_xor_sync(0xffffffffu, ps1, 2);
            ssum[0] = ssum[0] * cr0 + ps0;
            ssum[1] = ssum[1] * cr1 + ps1;
            if (t4 == 0) { corr_sm[l] = cr0; corr_sm[l + 8] = cr1; }
        }
        __syncthreads();

        {
            float c0r = corr_sm[wm2 + g], c1r = corr_sm[wm2 + 8 + g];
#pragma unroll
            for (int nf = 0; nf < 4; nf++) {
                cacc[nf][0] *= c0r; cacc[nf][1] *= c0r;
                cacc[nf][2] *= c1r; cacc[nf][3] *= c1r;
            }
            pv_tile(cacc, sb, wm2, wn2, lane);
        }
        __syncthreads();
    }

    if (warp < 4 && t4 == 0) {
        ((float*)(sm + A_SSI))[wm + g] = ssum[0];
        ((float*)(sm + A_SSI))[wm + g + 8] = ssum[1];
    }
    __syncthreads();

    {
        const float tg = tanhf(gate[h]);
        const float* stash = (const float*)(sm + A_STASH);
        const float* ssmv = (const float*)(sm + A_SSM);
        const float* ssiv = (const float*)(sm + A_SSI);
        const float rnm0 = 1.f / ssmv[wm2 + g], rni0 = tg / ssiv[wm2 + g];
        const float rnm1 = 1.f / ssmv[wm2 + 8 + g], rni1 = tg / ssiv[wm2 + 8 + g];
#pragma unroll
        for (int nf = 0; nf < 4; nf++) {
            const int d = wn2 + 8 * nf + 2 * t4;
            float2 o0, o1;
            o0.x = stash[(wm2 + g) * 68 + d] * rnm0 + cacc[nf][0] * rni0;
            o0.y = stash[(wm2 + g) * 68 + d + 1] * rnm0 + cacc[nf][1] * rni0;
            o1.x = stash[(wm2 + 8 + g) * 68 + d] * rnm1 + cacc[nf][2] * rni1;
            o1.y = stash[(wm2 + 8 + g) * 68 + d + 1] * rnm1 + cacc[nf][3] * rni1;
            *(float2*)(outp + ((size_t)(b * SQ + l0 + wm2 + g)) * HIDDEN + h * DH + d) = o0;
            *(float2*)(outp + ((size_t)(b * SQ + l0 + wm2 + 8 + g)) * HIDDEN + h * DH + d) = o1;
        }
    }
}

// ---------------------------------------------------------------------------
extern "C" void kernel_launch(void* const* d_in, const int* in_sizes, int n_in,
                              void* d_out, int out_size)
{
    (void)in_sizes; (void)n_in; (void)out_size;
    const float* hs    = (const float*)d_in[0];
    const float* amask = (const float*)d_in[1];
    const float* ihs   = (const float*)d_in[2];
    const float* imask = (const float*)d_in[3];
    const float* Wq    = (const float*)d_in[4];
    const float* bq    = (const float*)d_in[5];
    const float* Wk    = (const float*)d_in[6];
    const float* bk    = (const float*)d_in[7];
    const float* Wv    = (const float*)d_in[8];
    const float* bv    = (const float*)d_in[9];
    const float* gate  = (const float*)d_in[10];
    const float* dist  = (const float*)d_in[11];
    float* out = (float*)d_out;

    __half *qf, *kf, *vf, *ikf, *ivf, *ef, *xc, *ixc, *wc;
    cudaGetSymbolAddress((void**)&qf, g_Qf);
    cudaGetSymbolAddress((void**)&kf, g_Kf);
    cudaGetSymbolAddress((void**)&vf, g_Vf);
    cudaGetSymbolAddress((void**)&ikf, g_IKf);
    cudaGetSymbolAddress((void**)&ivf, g_IVf);
    cudaGetSymbolAddress((void**)&ef, g_Ef);
    cudaGetSymbolAddress((void**)&xc, g_Xh);
    cudaGetSymbolAddress((void**)&ixc, g_IXh);
    cudaGetSymbolAddress((void**)&wc, g_Wh);

    cudaFuncSetAttribute(gemm_mma, cudaFuncAttributeMaxDynamicSharedMemorySize, GEMM_SMEM);
    cudaFuncSetAttribute(attn_mma, cudaFuncAttributeMaxDynamicSharedMemorySize, A_TOTAL);

    conv_all<<<NX_BASE3 + NX_W, 256>>>((const float4*)hs, xc,
                                       (const float4*)ihs, ixc, dist, ef,
                                       Wq, Wk, Wv, wc);

    gemm_mma<<<416, 256, GEMM_SMEM>>>(xc, ixc, wc, bq, bk, bv,
                                      qf, kf, vf, ikf, ivf);

    attn_mma<<<dim3(SQ / 64, BHN), 256, A_TOTAL>>>(amask, imask, gate, out);
}